// round 10
// baseline (speedup 1.0000x reference)
#include <cuda_runtime.h>
#include <cuda_fp16.h>
#include <math.h>

#define NE    30      // electrons
#define NA    10      // atoms
#define NN    40      // en-graph nodes
#define FEAT  64
#define NPE   435     // ee unique pairs
#define NPN   300     // en unique pairs
#define NL    2
#define T_TAB 4096
#define INV_STEP 256.0f   // T_TAB / 16.0 range
#define BLK   512
#define NWARP (BLK / 32)

__device__ float g_tab_ee[T_TAB * FEAT];
__device__ float g_tab_en[T_TAB * FEAT];

__device__ __forceinline__ float tanh_fast(float x) {
    float cx = fminf(fmaxf(x, -15.f), 15.f);
    float e = __expf(2.f * cx);
    return __fdividef(e - 1.f, e + 1.f);
}

// ---------------------------------------------------------------------------
// Table build: grid (T_TAB/32, 2), block 256.
// ---------------------------------------------------------------------------
__global__ void build_tab_kernel(const float* __restrict__ wf_ee,
                                 const float* __restrict__ bf_ee,
                                 const float* __restrict__ wf_en,
                                 const float* __restrict__ bf_en) {
    __shared__ float s_wf[FEAT * FEAT];
    __shared__ float s_rbf[32][FEAT];
    const float* wf = blockIdx.y ? wf_en : wf_ee;
    const float* bf = blockIdx.y ? bf_en : bf_ee;
    float* tab      = blockIdx.y ? g_tab_en : g_tab_ee;

    const int t = threadIdx.x;
    for (int i = t; i < FEAT * FEAT; i += 256) s_wf[i] = wf[i];

    const int f  = t & 63;
    const int rg = t >> 6;
    const int base = blockIdx.x * 32;

    #pragma unroll
    for (int rr = 0; rr < 8; rr++) {
        int r = rg + rr * 4;
        float d = (float)(base + r) * (1.0f / INV_STEP);
        float x = d - (float)f * (8.0f / 63.0f);
        s_rbf[r][f] = __expf(-x * x);
    }
    __syncthreads();

    float bfv = bf[f];
    float a[8];
    #pragma unroll
    for (int rr = 0; rr < 8; rr++) a[rr] = bfv;
    #pragma unroll
    for (int k = 0; k < FEAT; k++) {
        float w = s_wf[k * FEAT + f];
        #pragma unroll
        for (int rr = 0; rr < 8; rr++)
            a[rr] = fmaf(s_rbf[rg + rr * 4][k], w, a[rr]);
    }
    #pragma unroll
    for (int rr = 0; rr < 8; rr++)
        tab[(base + rg + rr * 4) * FEAT + f] = tanhf(a[rr]);
}

// ---------------------------------------------------------------------------
struct __align__(16) Smem {
    __half2 filt2[NPE * 32];      // 55,680 B; en uses first 300*32, emb_en
                                  // aliased at byte offset 38,400 in en section
    float   h[NN * FEAT];         // 10,240
    float   agg[NN * FEAT];       // 10,240 (also distance scratch)
    float4  wlT[NL * 32 * 32];    // 32,768
    float   bl[NL * FEAT];        // 512
    float   wr[FEAT];             // 256
    float   embee[2 * FEAT];      // 512
    float   xyz[NE * 3];          // 360
    float   atm[NA * 3];          // 120
    float   red[NWARP];           // 64  (ee readout partials)
    float   red2[NWARP];          // 64  (en readout partials)
};                                 // ~110,816 B -> 2 CTAs/SM

__device__ __forceinline__ void stage_weights(Smem& S, const float* wl,
                                              const float* bl, const float* wr, int t) {
    for (int idx = t; idx < NL * 32 * 32; idx += BLK) {
        int l = idx >> 10, r = idx & 1023;
        int kk = r >> 5, fp = r & 31;
        const float* s0 = &wl[(l * FEAT + 2 * kk) * FEAT + 2 * fp];
        float4 v;
        v.x = s0[0]; v.y = s0[1];
        v.z = s0[FEAT]; v.w = s0[FEAT + 1];
        S.wlT[idx] = v;
    }
    for (int i = t; i < NL * FEAT; i += BLK) S.bl[i] = bl[i];
    if (t < FEAT) S.wr[t] = wr[t];
}

// core: compute tanh-args (agg @ wl + bl) for up to 4 nodes into ca[4].
// Plain FFMA form (no 64-bit broadcast packs).
__device__ __forceinline__ void linear4_core(Smem& S, int l, int node0, int nlim,
                                             int fp, float2 ca[4]) {
    float2 bias = *(const float2*)&S.bl[l * FEAT + 2 * fp];
    float2 aa[4], bb[4];
    #pragma unroll
    for (int s = 0; s < 4; s++) { aa[s] = bias; bb[s] = make_float2(0.f, 0.f); }
    const float4* wT = &S.wlT[l * 1024 + fp];
    #pragma unroll
    for (int kk = 0; kk < 32; kk += 2) {
        float4 w0 = wT[kk * 32];          // k=2kk   -> (x,y); k=2kk+1 -> (z,w)
        float4 w1 = wT[(kk + 1) * 32];    // k=2kk+2 -> (x,y); k=2kk+3 -> (z,w)
        #pragma unroll
        for (int s = 0; s < 4; s++) {
            int n = node0 + s;
            if (n < nlim) {
                float4 av = *(const float4*)&S.agg[n * FEAT + 2 * kk];  // broadcast
                aa[s].x = fmaf(av.x, w0.x, aa[s].x);
                aa[s].y = fmaf(av.x, w0.y, aa[s].y);
                bb[s].x = fmaf(av.y, w0.z, bb[s].x);
                bb[s].y = fmaf(av.y, w0.w, bb[s].y);
                aa[s].x = fmaf(av.z, w1.x, aa[s].x);
                aa[s].y = fmaf(av.z, w1.y, aa[s].y);
                bb[s].x = fmaf(av.w, w1.z, bb[s].x);
                bb[s].y = fmaf(av.w, w1.w, bb[s].y);
            }
        }
    }
    #pragma unroll
    for (int s = 0; s < 4; s++) {
        ca[s].x = aa[s].x + bb[s].x;
        ca[s].y = aa[s].y + bb[s].y;
    }
}

// layer-0 linear: h[n] = emb_row(n) + tanh(core); writes h.
template <bool EE>
__device__ __forceinline__ void linear4_l0(Smem& S, const float* embsrc,
                                           int node0, int nlim, int fp) {
    float2 ca[4];
    linear4_core(S, 0, node0, nlim, fp, ca);
    #pragma unroll
    for (int s = 0; s < 4; s++) {
        int n = node0 + s;
        if (n < nlim) {
            int ty = EE ? (n < 15 ? 0 : 1)
                        : (n < 15 ? 0 : (n < NE ? 1 : 2 + (n - NE)));
            float2 ev = *(const float2*)&embsrc[ty * FEAT + 2 * fp];
            ev.x += tanh_fast(ca[s].x);
            ev.y += tanh_fast(ca[s].y);
            *(float2*)&S.h[n * FEAT + 2 * fp] = ev;
        }
    }
}

// last-layer linear with readout fold: r += (h_prev + tanh(core)) . wr
__device__ __forceinline__ void linear4_fold(Smem& S, float* red, int warp,
                                             int node0, int nlim, int fp) {
    float2 ca[4];
    linear4_core(S, NL - 1, node0, nlim, fp, ca);
    float2 w = *(const float2*)&S.wr[2 * fp];
    float r = 0.f;
    #pragma unroll
    for (int s = 0; s < 4; s++) {
        int n = node0 + s;
        if (n < nlim) {
            float2 hv = *(const float2*)&S.h[n * FEAT + 2 * fp];
            r += (hv.x + tanh_fast(ca[s].x)) * w.x + (hv.y + tanh_fast(ca[s].y)) * w.y;
        }
    }
    #pragma unroll
    for (int o = 16; o; o >>= 1) r += __shfl_down_sync(0xffffffffu, r, o);
    if ((threadIdx.x & 31) == 0) red[warp] = r;
}

__global__ void __launch_bounds__(BLK, 2) jastrow_kernel(
    const float* __restrict__ pos,    const float* __restrict__ atoms,
    const float* __restrict__ emb_ee, const float* __restrict__ wl_ee,
    const float* __restrict__ bl_ee,  const float* __restrict__ wr_ee,
    const float* __restrict__ br_ee,
    const float* __restrict__ emb_en, const float* __restrict__ wl_en,
    const float* __restrict__ bl_en,  const float* __restrict__ wr_en,
    const float* __restrict__ br_en,
    float* __restrict__ out) {
    extern __shared__ char smem_raw[];
    Smem& S = *reinterpret_cast<Smem*>(smem_raw);
    float* Sd = S.agg;   // distance scratch (dead once filt2 is built)
    float* embeen = (float*)((char*)S.filt2 + NPN * 32 * sizeof(__half2)); // filt2 tail
    const int t = threadIdx.x;
    const int b = blockIdx.x;
    const int warp = t >> 5;
    const int fp = t & 31;

    for (int i = t; i < NE * 3; i += BLK) S.xyz[i] = pos[b * NE * 3 + i];
    for (int i = t; i < NA * 3; i += BLK) S.atm[i] = atoms[i];
    if (t < 2 * FEAT) S.embee[t] = emb_ee[t];
    stage_weights(S, wl_ee, bl_ee, wr_ee, t);
    __syncthreads();

    // ================= EE graph =================
    for (int x = t; x < NE * NE; x += BLK) {
        int i = x / NE, j = x % NE;
        if (i < j) {
            int p = ((i * (2 * NE - 1 - i)) >> 1) + j - i - 1;
            float dx = S.xyz[i * 3 + 0] - S.xyz[j * 3 + 0];
            float dy = S.xyz[i * 3 + 1] - S.xyz[j * 3 + 1];
            float dz = S.xyz[i * 3 + 2] - S.xyz[j * 3 + 2];
            Sd[p] = sqrtf(dx * dx + dy * dy + dz * dz);
        }
    }
    __syncthreads();

    for (int it = t; it < NPE * 32; it += BLK) {
        int p = it >> 5, f2 = it & 31;
        float u = fminf(Sd[p] * INV_STEP, (float)(T_TAB - 2) + 0.999f);
        int idx = (int)u;
        float w = u - (float)idx;
        float2 v0 = *(const float2*)&g_tab_ee[idx * FEAT + 2 * f2];
        float2 v1 = *(const float2*)&g_tab_ee[(idx + 1) * FEAT + 2 * f2];
        S.filt2[it] = __floats2half2_rn(fmaf(w, v1.x - v0.x, v0.x),
                                        fmaf(w, v1.y - v0.y, v0.y));
    }
    __syncthreads();

    // ---- layer 0: factored gather (h0 = emb[type]) ----
    if (warp < 15) {
        const int n0 = 2 * warp, n1 = n0 + 1;
        const int Bn0 = ((n0 * (2 * NE - 1 - n0)) >> 1) - n0 - 1;
        const int Bn1 = ((n1 * (2 * NE - 1 - n1)) >> 1) - n1 - 1;
        float2 su0 = {0, 0}, sd0 = {0, 0}, su1 = {0, 0}, sd1 = {0, 0};
        #pragma unroll
        for (int j = 0; j < NE; j++) {
            const int K1 = ((j * (2 * NE - 1 - j)) >> 1) - j - 1;
            if (j != n0) {
                int p = (j < n0) ? (K1 + n0) : (Bn0 + j);
                float2 fv = __half22float2(S.filt2[p * 32 + fp]);
                if (j < 15) { su0.x += fv.x; su0.y += fv.y; }
                else        { sd0.x += fv.x; sd0.y += fv.y; }
            }
            if (j != n1) {
                int p = (j < n1) ? (K1 + n1) : (Bn1 + j);
                float2 fv = __half22float2(S.filt2[p * 32 + fp]);
                if (j < 15) { su1.x += fv.x; su1.y += fv.y; }
                else        { sd1.x += fv.x; sd1.y += fv.y; }
            }
        }
        float2 e0 = *(const float2*)&S.embee[2 * fp];
        float2 e1 = *(const float2*)&S.embee[FEAT + 2 * fp];
        float2 a0, a1;
        a0.x = fmaf(sd0.x, e1.x, su0.x * e0.x);
        a0.y = fmaf(sd0.y, e1.y, su0.y * e0.y);
        a1.x = fmaf(sd1.x, e1.x, su1.x * e0.x);
        a1.y = fmaf(sd1.y, e1.y, su1.y * e0.y);
        *(float2*)&S.agg[n0 * FEAT + 2 * fp] = a0;
        *(float2*)&S.agg[n1 * FEAT + 2 * fp] = a1;
    }
    __syncthreads();
    if (warp < 8) linear4_l0<true>(S, S.embee, 4 * warp, NE, fp);
    __syncthreads();

    // ---- layer 1: full gather + fold ----
    if (warp < 15) {
        const int n0 = 2 * warp, n1 = n0 + 1;
        const int Bn0 = ((n0 * (2 * NE - 1 - n0)) >> 1) - n0 - 1;
        const int Bn1 = ((n1 * (2 * NE - 1 - n1)) >> 1) - n1 - 1;
        float2 a0a = {0, 0}, a0b = {0, 0}, a1a = {0, 0}, a1b = {0, 0};
        #pragma unroll
        for (int j = 0; j < NE; j++) {
            const int K1 = ((j * (2 * NE - 1 - j)) >> 1) - j - 1;
            float2 hv = *(const float2*)&S.h[j * FEAT + 2 * fp];
            if (j != n0) {
                int p = (j < n0) ? (K1 + n0) : (Bn0 + j);
                float2 fv = __half22float2(S.filt2[p * 32 + fp]);
                if (j & 1) { a0b.x = fmaf(hv.x, fv.x, a0b.x); a0b.y = fmaf(hv.y, fv.y, a0b.y); }
                else       { a0a.x = fmaf(hv.x, fv.x, a0a.x); a0a.y = fmaf(hv.y, fv.y, a0a.y); }
            }
            if (j != n1) {
                int p = (j < n1) ? (K1 + n1) : (Bn1 + j);
                float2 fv = __half22float2(S.filt2[p * 32 + fp]);
                if (j & 1) { a1b.x = fmaf(hv.x, fv.x, a1b.x); a1b.y = fmaf(hv.y, fv.y, a1b.y); }
                else       { a1a.x = fmaf(hv.x, fv.x, a1a.x); a1a.y = fmaf(hv.y, fv.y, a1a.y); }
            }
        }
        a0a.x += a0b.x; a0a.y += a0b.y;
        a1a.x += a1b.x; a1a.y += a1b.y;
        *(float2*)&S.agg[n0 * FEAT + 2 * fp] = a0a;
        *(float2*)&S.agg[n1 * FEAT + 2 * fp] = a1a;
    }
    __syncthreads();
    if (warp < 8) linear4_fold(S, S.red, warp, 4 * warp, NE, fp);
    __syncthreads();

    // ================= EN graph =================
    for (int q = t; q < NPN; q += BLK) {
        int a = q / NE, e = q % NE;
        float dx = S.xyz[e * 3 + 0] - S.atm[a * 3 + 0];
        float dy = S.xyz[e * 3 + 1] - S.atm[a * 3 + 1];
        float dz = S.xyz[e * 3 + 2] - S.atm[a * 3 + 2];
        Sd[q] = sqrtf(dx * dx + dy * dy + dz * dz);
    }
    stage_weights(S, wl_en, bl_en, wr_en, t);
    for (int i = t; i < (2 + NA) * FEAT; i += BLK) embeen[i] = emb_en[i];
    __syncthreads();

    for (int it = t; it < NPN * 32; it += BLK) {
        int q = it >> 5, f2 = it & 31;
        float u = fminf(Sd[q] * INV_STEP, (float)(T_TAB - 2) + 0.999f);
        int idx = (int)u;
        float w = u - (float)idx;
        float2 v0 = *(const float2*)&g_tab_en[idx * FEAT + 2 * f2];
        float2 v1 = *(const float2*)&g_tab_en[(idx + 1) * FEAT + 2 * f2];
        S.filt2[it] = __floats2half2_rn(fmaf(w, v1.x - v0.x, v0.x),
                                        fmaf(w, v1.y - v0.y, v0.y));
    }
    __syncthreads();

    // ---- layer 0: gather with emb sources ----
    if (warp < 10) {             // electron nodes, 3 each; atom h0 = emb rows
        const int base = 3 * warp;
        float2 acc[3] = {{0, 0}, {0, 0}, {0, 0}};
        #pragma unroll
        for (int aa = 0; aa < NA; aa++) {
            float2 hv = *(const float2*)&embeen[(2 + aa) * FEAT + 2 * fp];
            #pragma unroll
            for (int s = 0; s < 3; s++) {
                float2 fv = __half22float2(S.filt2[(aa * NE + base + s) * 32 + fp]);
                acc[s].x = fmaf(hv.x, fv.x, acc[s].x);
                acc[s].y = fmaf(hv.y, fv.y, acc[s].y);
            }
        }
        #pragma unroll
        for (int s = 0; s < 3; s++)
            *(float2*)&S.agg[(base + s) * FEAT + 2 * fp] = acc[s];
    } else if (warp < 15) {      // atom nodes, 2 each: factored over e-types
        const int a0 = 2 * (warp - 10), a1 = a0 + 1;
        float2 su0 = {0, 0}, sd0 = {0, 0}, su1 = {0, 0}, sd1 = {0, 0};
        #pragma unroll
        for (int e = 0; e < NE; e++) {
            float2 f0 = __half22float2(S.filt2[(a0 * NE + e) * 32 + fp]);
            float2 f1 = __half22float2(S.filt2[(a1 * NE + e) * 32 + fp]);
            if (e < 15) { su0.x += f0.x; su0.y += f0.y; su1.x += f1.x; su1.y += f1.y; }
            else        { sd0.x += f0.x; sd0.y += f0.y; sd1.x += f1.x; sd1.y += f1.y; }
        }
        float2 e0 = *(const float2*)&embeen[2 * fp];
        float2 e1 = *(const float2*)&embeen[FEAT + 2 * fp];
        float2 c0, c1;
        c0.x = fmaf(sd0.x, e1.x, su0.x * e0.x);
        c0.y = fmaf(sd0.y, e1.y, su0.y * e0.y);
        c1.x = fmaf(sd1.x, e1.x, su1.x * e0.x);
        c1.y = fmaf(sd1.y, e1.y, su1.y * e0.y);
        *(float2*)&S.agg[(NE + a0) * FEAT + 2 * fp] = c0;
        *(float2*)&S.agg[(NE + a1) * FEAT + 2 * fp] = c1;
    }
    __syncthreads();
    if (warp < 10) linear4_l0<false>(S, embeen, 4 * warp, NN, fp);
    __syncthreads();

    // ---- layer 1: full gather + fold ----
    if (warp < 10) {
        const int base = 3 * warp;
        float2 acc[3] = {{0, 0}, {0, 0}, {0, 0}};
        #pragma unroll
        for (int aa = 0; aa < NA; aa++) {
            float2 hv = *(const float2*)&S.h[(NE + aa) * FEAT + 2 * fp];
            #pragma unroll
            for (int s = 0; s < 3; s++) {
                float2 fv = __half22float2(S.filt2[(aa * NE + base + s) * 32 + fp]);
                acc[s].x = fmaf(hv.x, fv.x, acc[s].x);
                acc[s].y = fmaf(hv.y, fv.y, acc[s].y);
            }
        }
        #pragma unroll
        for (int s = 0; s < 3; s++)
            *(float2*)&S.agg[(base + s) * FEAT + 2 * fp] = acc[s];
    } else if (warp < 15) {
        const int a0 = 2 * (warp - 10), a1 = a0 + 1;
        float2 c0a = {0, 0}, c0b = {0, 0}, c1a = {0, 0}, c1b = {0, 0};
        #pragma unroll
        for (int e = 0; e < NE; e++) {
            float2 hv = *(const float2*)&S.h[e * FEAT + 2 * fp];
            float2 f0 = __half22float2(S.filt2[(a0 * NE + e) * 32 + fp]);
            float2 f1 = __half22float2(S.filt2[(a1 * NE + e) * 32 + fp]);
            if (e & 1) {
                c0b.x = fmaf(hv.x, f0.x, c0b.x); c0b.y = fmaf(hv.y, f0.y, c0b.y);
                c1b.x = fmaf(hv.x, f1.x, c1b.x); c1b.y = fmaf(hv.y, f1.y, c1b.y);
            } else {
                c0a.x = fmaf(hv.x, f0.x, c0a.x); c0a.y = fmaf(hv.y, f0.y, c0a.y);
                c1a.x = fmaf(hv.x, f1.x, c1a.x); c1a.y = fmaf(hv.y, f1.y, c1a.y);
            }
        }
        c0a.x += c0b.x; c0a.y += c0b.y;
        c1a.x += c1b.x; c1a.y += c1b.y;
        *(float2*)&S.agg[(NE + a0) * FEAT + 2 * fp] = c0a;
        *(float2*)&S.agg[(NE + a1) * FEAT + 2 * fp] = c1a;
    }
    __syncthreads();
    if (warp < 10) linear4_fold(S, S.red2, warp, 4 * warp, NN, fp);
    __syncthreads();

    if (t == 0) {
        float kee = br_ee[0], ken = br_en[0];
        #pragma unroll
        for (int w = 0; w < 8; w++) kee += S.red[w];
        #pragma unroll
        for (int w = 0; w < 10; w++) ken += S.red2[w];
        out[b] = expf(kee + ken);
    }
}

// ---------------------------------------------------------------------------
extern "C" void kernel_launch(void* const* d_in, const int* in_sizes, int n_in,
                              void* d_out, int out_size) {
    const float* pos    = (const float*)d_in[0];
    const float* atoms  = (const float*)d_in[1];
    const float* emb_ee = (const float*)d_in[2];
    const float* wf_ee  = (const float*)d_in[3];
    const float* bf_ee  = (const float*)d_in[4];
    const float* wl_ee  = (const float*)d_in[5];
    const float* bl_ee  = (const float*)d_in[6];
    const float* wr_ee  = (const float*)d_in[7];
    const float* br_ee  = (const float*)d_in[8];
    const float* emb_en = (const float*)d_in[9];
    const float* wf_en  = (const float*)d_in[10];
    const float* bf_en  = (const float*)d_in[11];
    const float* wl_en  = (const float*)d_in[12];
    const float* bl_en  = (const float*)d_in[13];
    const float* wr_en  = (const float*)d_in[14];
    const float* br_en  = (const float*)d_in[15];
    float* out = (float*)d_out;

    int nb = in_sizes[0] / (NE * 3);

    cudaFuncSetAttribute(jastrow_kernel,
                         cudaFuncAttributeMaxDynamicSharedMemorySize,
                         (int)sizeof(Smem));

    build_tab_kernel<<<dim3(T_TAB / 32, 2), 256>>>(wf_ee, bf_ee, wf_en, bf_en);
    jastrow_kernel<<<nb, BLK, sizeof(Smem)>>>(
        pos, atoms, emb_ee, wl_ee, bl_ee, wr_ee, br_ee,
        emb_en, wl_en, bl_en, wr_en, br_en, out);
}